// round 1
// baseline (speedup 1.0000x reference)
#include <cuda_runtime.h>

#define NND 2048
#define NF  32
#define NC  3
#define NH  35
#define H1  64
#define H2  32

// ---------------- scratch (device globals, no allocs) ----------------
__device__ __align__(16) float g_invn[NND];
__device__ __align__(16) float g_s[NND * NF];        // x^2 * invnorm
__device__ __align__(16) float g_S[NND * NF];        // exclusive prefix of g_s
__device__ __align__(16) float g_neigh1[NND * NH];
__device__ __align__(16) float g_h1[NND * H1];
__device__ __align__(16) float g_P1[NND * H1];       // exclusive prefix of h1
__device__ __align__(16) float g_A[NND * H2];        // h2 @ Wm1[0:32]  + bm1
__device__ __align__(16) float g_B[NND * H2];        // h2 @ Wm1[32:64]
__device__ __align__(16) float g_wd[H2];
__device__ float g_bd;

// ---------------- K1: norms + s = x^2/||x|| ----------------
__global__ void k_norm(const float* __restrict__ x) {
    int i = blockIdx.x * blockDim.x + threadIdx.x;
    if (i >= NND) return;
    float v[NF];
    float s = 0.f;
#pragma unroll
    for (int k = 0; k < NF; k++) { v[k] = x[i * NF + k]; s += v[k] * v[k]; }
    float invn = rsqrtf(s);
    g_invn[i] = invn;
#pragma unroll
    for (int k = 0; k < NF; k++) g_s[i * NF + k] = v[k] * v[k] * invn;
}

// ---------------- exclusive prefix scan over node dim ----------------
// WHICH=0: g_s[NND,32] -> g_S ; WHICH=1: g_h1[NND,64] -> g_P1
template <int F, int CH, int WHICH>
__global__ void k_scan() {
    const float* __restrict__ in = (WHICH == 0) ? g_s : g_h1;
    float* __restrict__ out      = (WHICH == 0) ? g_S : g_P1;
    const int LEN = NND / CH;
    __shared__ float part[CH * F];
    __shared__ float offs[CH * F];
    int t = threadIdx.x;            // blockDim = F*CH (<=1024)
    int f = t % F, ch = t / F;
    const float* p = in + (size_t)(ch * LEN) * F + f;
    float acc = 0.f;
#pragma unroll 4
    for (int r = 0; r < LEN; r++) acc += p[(size_t)r * F];
    part[ch * F + f] = acc;
    __syncthreads();
    if (ch == 0) {
        float run = 0.f;
        for (int c = 0; c < CH; c++) { offs[c * F + f] = run; run += part[c * F + f]; }
    }
    __syncthreads();
    float run = offs[ch * F + f];
    float* q = out + (size_t)(ch * LEN) * F + f;
    for (int r = 0; r < LEN; r++) { q[(size_t)r * F] = run; run += p[(size_t)r * F]; }
}

// ---------------- K2b: centroid |diff| aggregation + finalize neigh1 ----------------
__global__ void k_neigh1(const float* __restrict__ x, const float* __restrict__ cent) {
    int j = blockIdx.x;
    int t = threadIdx.x;  // 128
    float cj0 = cent[j * 3 + 0], cj1 = cent[j * 3 + 1], cj2 = cent[j * 3 + 2];
    float t0 = 0.f, t1 = 0.f, t2 = 0.f;
    for (int i = t; i < j; i += 128) {
        float a = cent[i * 3 + 0], b = cent[i * 3 + 1], c = cent[i * 3 + 2];
        t0 += a * fabsf(a - cj0);
        t1 += b * fabsf(b - cj1);
        t2 += c * fabsf(c - cj2);
    }
    __shared__ float red[3][128];
    red[0][t] = t0; red[1][t] = t1; red[2][t] = t2;
    __syncthreads();
    for (int s = 64; s > 0; s >>= 1) {
        if (t < s) {
            red[0][t] += red[0][t + s];
            red[1][t] += red[1][t + s];
            red[2][t] += red[2][t + s];
        }
        __syncthreads();
    }
    float invdeg = (j > 0) ? (1.f / (float)j) : 0.f;
    if (t < NF) {
        g_neigh1[j * NH + t] = invdeg * x[j * NF + t] * g_invn[j] * g_S[j * NF + t];
    } else if (t < NH) {
        g_neigh1[j * NH + t] = invdeg * red[t - NF][0];
    }
}

// ---------------- K3: h1 = h@Ws1 + neigh1@Wn1 + b1 ----------------
__global__ void k_h1(const float* __restrict__ x, const float* __restrict__ cent,
                     const float* __restrict__ Ws1, const float* __restrict__ Wn1,
                     const float* __restrict__ b1) {
    int t = blockIdx.x * blockDim.x + threadIdx.x;
    if (t >= NND * H1) return;
    int node = t / H1, f = t % H1;
    float acc = b1[f];
#pragma unroll
    for (int c = 0; c < NH; c++) {
        float hv = (c < NF) ? x[node * NF + c] : cent[node * NC + (c - NF)];
        acc += hv * Ws1[c * H1 + f] + g_neigh1[node * NH + c] * Wn1[c * H1 + f];
    }
    g_h1[t] = acc;
}

// ---------------- K5: h2 then A,B (fused) + wd/bd ----------------
__global__ void k_h2AB(const float* __restrict__ Ws2, const float* __restrict__ Wn2,
                       const float* __restrict__ b2, const float* __restrict__ Wm1,
                       const float* __restrict__ bm1, const float* __restrict__ Wm2,
                       const float* __restrict__ bm2) {
    __shared__ float h2s[8][H2 + 1];
    int ty = threadIdx.x / H2, f = threadIdx.x % H2;  // 256 threads: 8 nodes x 32 f
    int node = blockIdx.x * 8 + ty;
    float invdeg = (node > 0) ? (1.f / (float)node) : 0.f;
    float acc = b2[f];
#pragma unroll 8
    for (int c = 0; c < H1; c++) {
        float h1v = g_h1[node * H1 + c];
        float n2  = g_P1[node * H1 + c] * invdeg;
        acc += h1v * Ws2[c * H2 + f] + n2 * Wn2[c * H2 + f];
    }
    h2s[ty][f] = acc;
    __syncthreads();
    float accA = bm1[f], accB = 0.f;
#pragma unroll
    for (int c = 0; c < H2; c++) {
        float v = h2s[ty][c];
        accA += v * Wm1[c * H2 + f];
        accB += v * Wm1[(H2 + c) * H2 + f];
    }
    g_A[node * H2 + f] = accA;
    g_B[node * H2 + f] = accB;
    if (blockIdx.x == 0 && ty == 0) {
        g_wd[f] = Wm2[f * 2 + 0] - Wm2[f * 2 + 1];
        if (f == 0) g_bd = bm2[0] - bm2[1];
    }
}

// ---------------- K7: edge kernel ----------------
#define TTI 64
#define TTJ 128
__global__ void __launch_bounds__(256) k_edge(float* __restrict__ out) {
    int ti = blockIdx.y, tj = blockIdx.x;
    int i0 = ti * TTI, j0 = tj * TTJ;
    if (j0 + TTJ - 1 <= i0) return;  // entire tile has j <= i

    __shared__ float sA[TTI][33];
    __shared__ float sB[TTJ][33];
    __shared__ float swd[H2];
    __shared__ float sbd;

    int t = threadIdx.x;  // 256
    {
        const float4* gA4 = (const float4*)(g_A + (size_t)i0 * H2);
        for (int v = t; v < TTI * 8; v += 256) {
            float4 q = gA4[v];
            int r = v >> 3, c = (v & 7) * 4;
            sA[r][c] = q.x; sA[r][c + 1] = q.y; sA[r][c + 2] = q.z; sA[r][c + 3] = q.w;
        }
        const float4* gB4 = (const float4*)(g_B + (size_t)j0 * H2);
        for (int v = t; v < TTJ * 8; v += 256) {
            float4 q = gB4[v];
            int r = v >> 3, c = (v & 7) * 4;
            sB[r][c] = q.x; sB[r][c + 1] = q.y; sB[r][c + 2] = q.z; sB[r][c + 3] = q.w;
        }
        if (t < H2) swd[t] = g_wd[t];
        if (t == 0) sbd = g_bd;
    }
    __syncthreads();

    int tx = t & 15, ty = t >> 4;  // 16 x 16
    float acc[4][8];
#pragma unroll
    for (int a = 0; a < 4; a++)
#pragma unroll
        for (int b = 0; b < 8; b++) acc[a][b] = 0.f;

#pragma unroll 8
    for (int k = 0; k < H2; k++) {
        float w = swd[k];
        float av[4], bv[8];
#pragma unroll
        for (int a = 0; a < 4; a++) av[a] = sA[ty * 4 + a][k];
#pragma unroll
        for (int b = 0; b < 8; b++) bv[b] = sB[tx + 16 * b][k];
#pragma unroll
        for (int a = 0; a < 4; a++)
#pragma unroll
            for (int b = 0; b < 8; b++)
                acc[a][b] += fmaxf(av[a] + bv[b], 0.f) * w;
    }

    float bd = sbd;
#pragma unroll
    for (int a = 0; a < 4; a++) {
        int i = i0 + ty * 4 + a;
        int basei = i * (2 * NND - 1 - i) / 2;  // #edges with src < i
#pragma unroll
        for (int b = 0; b < 8; b++) {
            int j = j0 + tx + 16 * b;
            if (j > i) {
                float d  = acc[a][b] + bd;       // z0 - z1
                float ex = __expf(-d);
                float p0 = __fdividef(1.f, 1.f + ex);
                float p1 = 1.f - p0;
                int e = basei + (j - i - 1);
                ((float2*)out)[e] = make_float2(p0, p1);
            }
        }
    }
}

// ---------------- launch ----------------
extern "C" void kernel_launch(void* const* d_in, const int* in_sizes, int n_in,
                              void* d_out, int out_size) {
    const float* x    = (const float*)d_in[0];
    const float* cent = (const float*)d_in[1];
    const float* Ws1  = (const float*)d_in[2];
    const float* Wn1  = (const float*)d_in[3];
    const float* b1   = (const float*)d_in[4];
    const float* Ws2  = (const float*)d_in[5];
    const float* Wn2  = (const float*)d_in[6];
    const float* b2   = (const float*)d_in[7];
    const float* Wm1  = (const float*)d_in[8];
    const float* bm1  = (const float*)d_in[9];
    const float* Wm2  = (const float*)d_in[10];
    const float* bm2  = (const float*)d_in[11];
    float* out = (float*)d_out;

    k_norm<<<(NND + 255) / 256, 256>>>(x);
    k_scan<NF, 32, 0><<<1, NF * 32>>>();          // g_s -> g_S
    k_neigh1<<<NND, 128>>>(x, cent);
    k_h1<<<(NND * H1 + 255) / 256, 256>>>(x, cent, Ws1, Wn1, b1);
    k_scan<H1, 16, 1><<<1, H1 * 16>>>();          // g_h1 -> g_P1
    k_h2AB<<<NND / 8, 256>>>(Ws2, Wn2, b2, Wm1, bm1, Wm2, bm2);

    dim3 grid(NND / TTJ, NND / TTI);              // (tj=16, ti=32)
    k_edge<<<grid, 256>>>(out);
}

// round 6
// speedup vs baseline: 1.6189x; 1.6189x over previous
#include <cuda_runtime.h>

#define NND 2048
#define NF  32
#define NC  3
#define NH  35
#define H1  64
#define H2  32

// ---------------- scratch (device globals, no allocs) ----------------
__device__ __align__(16) float g_invn[NND];
__device__ __align__(16) float g_s[NND * NF];         // x^2 * invnorm
__device__ __align__(16) float g_partA[64 * NF];      // chunk sums of g_s (32-row chunks)
__device__ __align__(16) float g_S[NND * NF];         // exclusive prefix of g_s
__device__ __align__(16) float g_credp[16 * NND * 3]; // per-i-tile centroid partials
__device__ __align__(16) float g_h1[NND * H1];
__device__ __align__(16) float g_partB[128 * H1];     // chunk sums of h1 (16-row chunks)
__device__ __align__(16) float g_P1[NND * H1];        // exclusive prefix of h1
__device__ __align__(16) float g_A[NND * H2];         // h2 @ Wm1[0:32] + bm1
__device__ __align__(16) float g_B[NND * H2];         // h2 @ Wm1[32:64]
__device__ __align__(16) float g_wd[H2];
__device__ float g_bd;

// ---------------- K1: norms + s = x^2/||x|| + chunk partial sums ----------------
// grid 64, block 1024 (warp = one row: 32 rows x 32 f)
__global__ void __launch_bounds__(1024) k_normsum(const float* __restrict__ x) {
    int t = threadIdx.x;
    int f = t & 31, r = t >> 5;
    int node = blockIdx.x * 32 + r;
    float v = x[node * NF + f];
    float sq = v * v;
    float sum = sq;
#pragma unroll
    for (int m = 16; m > 0; m >>= 1) sum += __shfl_xor_sync(0xffffffffu, sum, m);
    float invn = rsqrtf(sum);
    if (f == 0) g_invn[node] = invn;
    float s = sq * invn;
    g_s[node * NF + f] = s;

    __shared__ float sm[32][33];
    sm[r][f] = s;
    __syncthreads();
#pragma unroll
    for (int str = 16; str > 0; str >>= 1) {
        if (r < str) sm[r][f] += sm[r + str][f];
        __syncthreads();
    }
    if (r == 0) g_partA[blockIdx.x * NF + f] = sm[0][f];
}

// ---------------- K2: scan-A apply (exclusive prefix of g_s) ----------------
// grid 64, block 32
__global__ void k_scanA_apply() {
    int f = threadIdx.x;
    int blk = blockIdx.x;
    float off = 0.f;
    for (int c = 0; c < blk; c++) off += g_partA[c * NF + f];
    float run = off;
    int base = blk * 32;
#pragma unroll
    for (int r = 0; r < 32; r++) {
        g_S[(base + r) * NF + f] = run;
        run += g_s[(base + r) * NF + f];
    }
}

// ---------------- K3: centroid |diff| tile partials (deterministic) ----------------
// grid (16 bj, 16 bi), keep bi <= bj; block 128 threads = one j each
__global__ void __launch_bounds__(128) k_credp(const float* __restrict__ cent) {
    int bj = blockIdx.x, bi = blockIdx.y;
    if (bi > bj) return;
    int t = threadIdx.x;
    __shared__ float scx[128], scy[128], scz[128];
    int i0 = bi * 128;
    scx[t] = cent[(i0 + t) * 3 + 0];
    scy[t] = cent[(i0 + t) * 3 + 1];
    scz[t] = cent[(i0 + t) * 3 + 2];
    __syncthreads();
    int j = bj * 128 + t;
    float cj0 = cent[j * 3 + 0], cj1 = cent[j * 3 + 1], cj2 = cent[j * 3 + 2];
    float t0 = 0.f, t1 = 0.f, t2 = 0.f;
    int lim = (bi == bj) ? t : 128;  // diag: i < j
    for (int il = 0; il < lim; il++) {
        float a = scx[il], b = scy[il], c = scz[il];
        t0 += a * fabsf(a - cj0);
        t1 += b * fabsf(b - cj1);
        t2 += c * fabsf(c - cj2);
    }
    size_t o = ((size_t)bi * NND + j) * 3;
    g_credp[o + 0] = t0;
    g_credp[o + 1] = t1;
    g_credp[o + 2] = t2;
}

// ---------------- K4: h1 GEMM (neigh1 finalize fused) + chunk partials ----------------
// grid 128 (16 nodes each), block 512
__global__ void __launch_bounds__(512) k_h1f(const float* __restrict__ x,
                                             const float* __restrict__ cent,
                                             const float* __restrict__ Ws1,
                                             const float* __restrict__ Wn1,
                                             const float* __restrict__ b1) {
    __shared__ float sWs[NH][H1];
    __shared__ float sWn[NH][H1];
    __shared__ float sH[16][36];
    __shared__ float sN[16][36];
    __shared__ float sRed[16][H1 + 1];

    int t = threadIdx.x;
    int blk = blockIdx.x;
    int nbase = blk * 16;

    // stage weights
    for (int idx = t; idx < NH * H1; idx += 512) {
        sWs[idx / H1][idx % H1] = Ws1[idx];
        sWn[idx / H1][idx % H1] = Wn1[idx];
    }
    // stage h rows + neigh1 rows
    for (int idx = t; idx < 16 * NH; idx += 512) {
        int n = idx / NH, c = idx % NH;
        int node = nbase + n;
        float invdeg = (node > 0) ? (1.f / (float)node) : 0.f;
        float hv, nv;
        if (c < NF) {
            hv = x[node * NF + c];
            nv = invdeg * hv * g_invn[node] * g_S[node * NF + c];
        } else {
            int d = c - NF;
            hv = cent[node * NC + d];
            float acc = 0.f;
            for (int ti = 0; ti * 128 < node; ti++)
                acc += g_credp[((size_t)ti * NND + node) * 3 + d];
            nv = invdeg * acc;
        }
        sH[n][c] = hv;
        sN[n][c] = nv;
    }
    __syncthreads();

    int f = t & 63, g = t >> 6;  // g in 0..7, handles nodes g and g+8
    float acc0 = b1[f], acc1 = acc0;
#pragma unroll
    for (int c = 0; c < NH; c++) {
        float ws = sWs[c][f], wn = sWn[c][f];
        acc0 += sH[g][c] * ws + sN[g][c] * wn;
        acc1 += sH[g + 8][c] * ws + sN[g + 8][c] * wn;
    }
    g_h1[(nbase + g) * H1 + f] = acc0;
    g_h1[(nbase + g + 8) * H1 + f] = acc1;

    // chunk partial over 16 nodes (tree reduce over node dim)
    sRed[g][f] = acc0 + acc1;
    __syncthreads();
    if (g < 4) sRed[g][f] += sRed[g + 4][f];
    __syncthreads();
    if (g < 2) sRed[g][f] += sRed[g + 2][f];
    __syncthreads();
    if (g == 0) g_partB[blk * H1 + f] = sRed[0][f] + sRed[1][f];
}

// ---------------- K5: scan-B apply (exclusive prefix of g_h1) ----------------
// grid 128, block 64
__global__ void k_scanB_apply() {
    int f = threadIdx.x;
    int blk = blockIdx.x;
    float off = 0.f;
    for (int c = 0; c < blk; c++) off += g_partB[c * H1 + f];
    float run = off;
    int base = blk * 16;
#pragma unroll
    for (int r = 0; r < 16; r++) {
        g_P1[(base + r) * H1 + f] = run;
        run += g_h1[(base + r) * H1 + f];
    }
}

// ---------------- K6: h2 then A,B (fused) + wd/bd ----------------
__global__ void k_h2AB(const float* __restrict__ Ws2, const float* __restrict__ Wn2,
                       const float* __restrict__ b2, const float* __restrict__ Wm1,
                       const float* __restrict__ bm1, const float* __restrict__ Wm2,
                       const float* __restrict__ bm2) {
    __shared__ float h2s[8][H2 + 1];
    int ty = threadIdx.x / H2, f = threadIdx.x % H2;  // 256 threads: 8 nodes x 32 f
    int node = blockIdx.x * 8 + ty;
    float invdeg = (node > 0) ? (1.f / (float)node) : 0.f;
    float acc = b2[f];
#pragma unroll 8
    for (int c = 0; c < H1; c++) {
        float h1v = g_h1[node * H1 + c];
        float n2  = g_P1[node * H1 + c] * invdeg;
        acc += h1v * Ws2[c * H2 + f] + n2 * Wn2[c * H2 + f];
    }
    h2s[ty][f] = acc;
    __syncthreads();
    float accA = bm1[f], accB = 0.f;
#pragma unroll
    for (int c = 0; c < H2; c++) {
        float v = h2s[ty][c];
        accA += v * Wm1[c * H2 + f];
        accB += v * Wm1[(H2 + c) * H2 + f];
    }
    g_A[node * H2 + f] = accA;
    g_B[node * H2 + f] = accB;
    if (blockIdx.x == 0 && ty == 0) {
        g_wd[f] = Wm2[f * 2 + 0] - Wm2[f * 2 + 1];
        if (f == 0) g_bd = bm2[0] - bm2[1];
    }
}

// ---------------- K7: edge kernel (128x128 tiles, 8x8 per thread) ----------------
#define TT 128
#define TSTR 132   // row stride: multiple of 4 floats -> every row base 16B-aligned
__global__ void __launch_bounds__(256) k_edge(float* __restrict__ out) {
    int bj = blockIdx.x, bi = blockIdx.y;
    if (bi > bj) return;
    int i0 = bi * TT, j0 = bj * TT;

    __shared__ float sAt[H2][TSTR];  // k-major
    __shared__ float sBt[H2][TSTR];
    __shared__ float swd[H2];
    __shared__ float sbd;

    int t = threadIdx.x;  // 256
    {
        const float4* gA4 = (const float4*)(g_A + (size_t)i0 * H2);
        const float4* gB4 = (const float4*)(g_B + (size_t)j0 * H2);
        for (int v = t; v < TT * 8; v += 256) {
            int r = v >> 3, c = (v & 7) * 4;
            float4 qa = gA4[v];
            sAt[c + 0][r] = qa.x; sAt[c + 1][r] = qa.y;
            sAt[c + 2][r] = qa.z; sAt[c + 3][r] = qa.w;
            float4 qb = gB4[v];
            sBt[c + 0][r] = qb.x; sBt[c + 1][r] = qb.y;
            sBt[c + 2][r] = qb.z; sBt[c + 3][r] = qb.w;
        }
        if (t < H2) swd[t] = g_wd[t];
        if (t == 0) sbd = g_bd;
    }
    __syncthreads();

    int tx = t & 15, ty = t >> 4;  // 16 x 16
    float acc[8][8];
#pragma unroll
    for (int a = 0; a < 8; a++)
#pragma unroll
        for (int b = 0; b < 8; b++) acc[a][b] = 0.f;

#pragma unroll 4
    for (int k = 0; k < H2; k++) {
        float w = swd[k];
        float av[8], bv[8];
        float4 a0 = *(const float4*)&sAt[k][ty * 8];      // 16B-aligned (stride 132)
        float4 a1 = *(const float4*)&sAt[k][ty * 8 + 4];
        av[0] = a0.x; av[1] = a0.y; av[2] = a0.z; av[3] = a0.w;
        av[4] = a1.x; av[5] = a1.y; av[6] = a1.z; av[7] = a1.w;
#pragma unroll
        for (int b = 0; b < 8; b++) bv[b] = sBt[k][tx + 16 * b];
#pragma unroll
        for (int a = 0; a < 8; a++)
#pragma unroll
            for (int b = 0; b < 8; b++)
                acc[a][b] += fmaxf(av[a] + bv[b], 0.f) * w;
    }

    float bd = sbd;
#pragma unroll
    for (int a = 0; a < 8; a++) {
        int i = i0 + ty * 8 + a;
        int basei = i * (2 * NND - 1 - i) / 2;  // #edges with src < i
#pragma unroll
        for (int b = 0; b < 8; b++) {
            int j = j0 + tx + 16 * b;
            if (j > i) {
                float d  = acc[a][b] + bd;  // z0 - z1
                float ex = __expf(-d);
                float p0 = __fdividef(1.f, 1.f + ex);
                float p1 = 1.f - p0;
                int e = basei + (j - i - 1);
                ((float2*)out)[e] = make_float2(p0, p1);
            }
        }
    }
}

// ---------------- launch ----------------
extern "C" void kernel_launch(void* const* d_in, const int* in_sizes, int n_in,
                              void* d_out, int out_size) {
    const float* x    = (const float*)d_in[0];
    const float* cent = (const float*)d_in[1];
    const float* Ws1  = (const float*)d_in[2];
    const float* Wn1  = (const float*)d_in[3];
    const float* b1   = (const float*)d_in[4];
    const float* Ws2  = (const float*)d_in[5];
    const float* Wn2  = (const float*)d_in[6];
    const float* b2   = (const float*)d_in[7];
    const float* Wm1  = (const float*)d_in[8];
    const float* bm1  = (const float*)d_in[9];
    const float* Wm2  = (const float*)d_in[10];
    const float* bm2  = (const float*)d_in[11];
    float* out = (float*)d_out;

    k_normsum<<<64, 1024>>>(x);
    k_scanA_apply<<<64, 32>>>();
    k_credp<<<dim3(16, 16), 128>>>(cent);
    k_h1f<<<128, 512>>>(x, cent, Ws1, Wn1, b1);
    k_scanB_apply<<<128, 64>>>();
    k_h2AB<<<NND / 8, 256>>>(Ws2, Wn2, b2, Wm1, bm1, Wm2, bm2);
    k_edge<<<dim3(16, 16), 256>>>(out);
}

// round 7
// speedup vs baseline: 2.2272x; 1.3757x over previous
#include <cuda_runtime.h>

#define NND 2048
#define NF  32
#define NC  3
#define NH  35
#define H1  64
#define H2  32

// ---------------- scratch (device globals, no allocs) ----------------
__device__ __align__(16) float g_invn[NND];
__device__ __align__(16) float g_s[NND * NF];          // x^2 * invnorm
__device__ __align__(16) float g_partA[128 * NF];      // chunk sums of g_s (16-row chunks)
__device__ __align__(16) float g_credp[16 * NND * 3];  // per-i-tile centroid partials
__device__ __align__(16) float g_h1[NND * H1];
__device__ __align__(16) float g_partB[128 * H1];      // chunk sums of h1 (16-row chunks)
__device__ __align__(16) float g_A[NND * H2];          // h2 @ Wm1[0:32] + bm1
__device__ __align__(16) float g_B[NND * H2];          // h2 @ Wm1[32:64]
__device__ __align__(16) float g_wd[H2];
__device__ float g_bd;

// ================ K1: norm/partials (blocks 0..127) + centroid tiles (128..263) ================
__global__ void __launch_bounds__(512) k_pre(const float* __restrict__ x,
                                             const float* __restrict__ cent) {
    int blk = blockIdx.x;
    int t = threadIdx.x;
    if (blk < 128) {
        // normsum: 16 nodes/block, warp lane = feature
        int f = t & 31, r = t >> 5;
        int node = blk * 16 + r;
        float v = x[node * NF + f];
        float sq = v * v;
        float sum = sq;
#pragma unroll
        for (int m = 16; m > 0; m >>= 1) sum += __shfl_xor_sync(0xffffffffu, sum, m);
        float invn = rsqrtf(sum);
        if (f == 0) g_invn[node] = invn;
        float s = sq * invn;
        g_s[node * NF + f] = s;
        __shared__ float sm[16][33];
        sm[r][f] = s;
        __syncthreads();
        if (r < 8) sm[r][f] += sm[r + 8][f];
        __syncthreads();
        if (r < 4) sm[r][f] += sm[r + 4][f];
        __syncthreads();
        if (r < 2) sm[r][f] += sm[r + 2][f];
        __syncthreads();
        if (r == 0) g_partA[blk * NF + f] = sm[0][f] + sm[1][f];
    } else {
        // centroid |diff| tile partials: 136 triangular blocks, 128 threads active
        if (t >= 128) return;
        int rr = blk - 128;
        int bj = 0;
        while (rr >= bj + 1) { rr -= bj + 1; bj++; }
        int bi = rr;  // bi <= bj
        __shared__ float sc[3][128];
        int i0 = bi * 128;
        sc[0][t] = cent[(i0 + t) * 3 + 0];
        sc[1][t] = cent[(i0 + t) * 3 + 1];
        sc[2][t] = cent[(i0 + t) * 3 + 2];
        __syncthreads();
        int j = bj * 128 + t;
        float cj0 = cent[j * 3 + 0], cj1 = cent[j * 3 + 1], cj2 = cent[j * 3 + 2];
        int lim = j - i0;
        if (lim > 128) lim = 128;
        float t0 = 0.f, t1 = 0.f, t2 = 0.f;
        for (int il = 0; il < lim; il++) {
            float a = sc[0][il], b = sc[1][il], c = sc[2][il];
            t0 += a * fabsf(a - cj0);
            t1 += b * fabsf(b - cj1);
            t2 += c * fabsf(c - cj2);
        }
        size_t o = ((size_t)bi * NND + j) * 3;
        g_credp[o + 0] = t0;
        g_credp[o + 1] = t1;
        g_credp[o + 2] = t2;
    }
}

// ================ K2: h1 GEMM with fused scan-A offset + cred sums + partB ================
// grid 128, block 512, 16 nodes/block
__global__ void __launch_bounds__(512) k_h1f(const float* __restrict__ x,
                                             const float* __restrict__ cent,
                                             const float* __restrict__ Ws1,
                                             const float* __restrict__ Wn1,
                                             const float* __restrict__ b1) {
    __shared__ float sWs[NH][H1];
    __shared__ float sWn[NH][H1];
    __shared__ float sg[16][33];     // g_s rows for local scan
    __shared__ float soff[NF];       // scan-A block offset
    __shared__ float scred[16][3];   // cred sums per node
    __shared__ float sH[16][36];
    __shared__ float sN[16][36];
    __shared__ float sRed[16][H1 + 1];

    int t = threadIdx.x;
    int blk = blockIdx.x;
    int nbase = blk * 16;

    // --- Phase A (all independent) ---
    for (int idx = t; idx < NH * H1; idx += 512) {
        sWs[idx / H1][idx % H1] = Ws1[idx];
        sWn[idx / H1][idx % H1] = Wn1[idx];
    }
    {
        int f = t & 31, n = t >> 5;
        sg[n][f] = g_s[(nbase + n) * NF + f];
    }
    if (t < 32) {  // scan-A offset: sum of chunk partials before this block
        int f = t;
        float o0 = 0.f, o1 = 0.f, o2 = 0.f, o3 = 0.f;
        int c = 0;
        for (; c + 4 <= blk; c += 4) {
            o0 += g_partA[(c + 0) * NF + f];
            o1 += g_partA[(c + 1) * NF + f];
            o2 += g_partA[(c + 2) * NF + f];
            o3 += g_partA[(c + 3) * NF + f];
        }
        for (; c < blk; c++) o0 += g_partA[c * NF + f];
        soff[f] = (o0 + o1) + (o2 + o3);
    }
    if (t >= 64 && t < 64 + 48) {  // cred sums
        int nd = t - 64;
        int n = nd / 3, d = nd % 3;
        int node = nbase + n;
        int nt = (node + 127) >> 7;  // tiles with ti*128 < node
        float a0 = 0.f, a1 = 0.f;
        int ti = 0;
        for (; ti + 2 <= nt; ti += 2) {
            a0 += g_credp[((size_t)(ti + 0) * NND + node) * 3 + d];
            a1 += g_credp[((size_t)(ti + 1) * NND + node) * 3 + d];
        }
        if (ti < nt) a0 += g_credp[((size_t)ti * NND + node) * 3 + d];
        scred[n][d] = a0 + a1;
    }
    __syncthreads();

    // --- Phase B: build sH (raw features) and sN (neigh1) ---
    for (int idx = t; idx < 16 * NH; idx += 512) {
        int n = idx / NH, c = idx % NH;
        int node = nbase + n;
        float invdeg = (node > 0) ? (1.f / (float)node) : 0.f;
        float hv, nv;
        if (c < NF) {
            hv = x[node * NF + c];
            float S = soff[c];
            for (int r = 0; r < n; r++) S += sg[r][c];
            nv = invdeg * hv * g_invn[node] * S;
        } else {
            int d = c - NF;
            hv = cent[node * NC + d];
            nv = invdeg * scred[n][d];
        }
        sH[n][c] = hv;
        sN[n][c] = nv;
    }
    __syncthreads();

    // --- Phase C: GEMM + partB ---
    int f = t & 63, g = t >> 6;  // g in 0..7 -> nodes g and g+8
    float acc0 = b1[f], acc1 = acc0;
#pragma unroll
    for (int c = 0; c < NH; c++) {
        float ws = sWs[c][f], wn = sWn[c][f];
        acc0 += sH[g][c] * ws + sN[g][c] * wn;
        acc1 += sH[g + 8][c] * ws + sN[g + 8][c] * wn;
    }
    g_h1[(nbase + g) * H1 + f] = acc0;
    g_h1[(nbase + g + 8) * H1 + f] = acc1;

    sRed[g][f] = acc0 + acc1;
    __syncthreads();
    if (g < 4) sRed[g][f] += sRed[g + 4][f];
    __syncthreads();
    if (g < 2) sRed[g][f] += sRed[g + 2][f];
    __syncthreads();
    if (g == 0) g_partB[blk * H1 + f] = sRed[0][f] + sRed[1][f];
}

// ================ K3: h2 + A/B with fused scan-B prefix ================
// grid 256, block 256, 8 nodes/block
__global__ void __launch_bounds__(256) k_h2AB(const float* __restrict__ b2,
                                              const float* __restrict__ Ws2,
                                              const float* __restrict__ Wn2,
                                              const float* __restrict__ Wm1,
                                              const float* __restrict__ bm1,
                                              const float* __restrict__ Wm2,
                                              const float* __restrict__ bm2) {
    __shared__ float sWs2[H1][H2];
    __shared__ float sWn2[H1][H2];
    __shared__ float sWm1[H1][H2];
    __shared__ float sHx[16][H1 + 1];   // full 16-chunk of h1 rows
    __shared__ float sP1[8][H1 + 1];    // neigh2 = P1 * invdeg (premultiplied)
    __shared__ float h2s[8][H2 + 1];
    __shared__ float soffB[H1];
    __shared__ float red[4][H1];

    int t = threadIdx.x;
    int blk = blockIdx.x;
    int nbase = blk * 8;
    int chunkbase = nbase & ~15;
    int own0 = nbase - chunkbase;  // 0 or 8

    // --- Phase A ---
    for (int idx = t; idx < H1 * H2; idx += 256) {
        sWs2[idx / H2][idx % H2] = Ws2[idx];
        sWn2[idx / H2][idx % H2] = Wn2[idx];
        sWm1[idx / H2][idx % H2] = Wm1[idx];
    }
    for (int idx = t; idx < 16 * H1; idx += 256) {
        int r = idx >> 6, c = idx & 63;
        sHx[r][c] = g_h1[(chunkbase + r) * H1 + c];
    }
    {   // scan-B chunk offsets: sum partB[ch][c] for ch < blk>>1, split 4 ways
        int grp = t >> 6, c = t & 63;
        int CB = blk >> 1;
        float acc = 0.f;
        for (int ch = grp; ch < CB; ch += 4) acc += g_partB[ch * H1 + c];
        red[grp][c] = acc;
    }
    __syncthreads();
    if (t < 64) soffB[t] = ((red[0][t] + red[1][t]) + (red[2][t] + red[3][t]));
    __syncthreads();
    // P1 (premultiplied by invdeg)
    for (int e = t; e < 8 * H1; e += 256) {
        int n = e >> 6, c = e & 63;
        int node = nbase + n;
        int L = node - chunkbase;
        float s = soffB[c];
        for (int r = 0; r < L; r++) s += sHx[r][c];
        float invdeg = (node > 0) ? (1.f / (float)node) : 0.f;
        sP1[n][c] = s * invdeg;
    }
    __syncthreads();

    // --- Phase B: h2 then A,B ---
    int ty = t >> 5, f = t & 31;
    float acc = b2[f];
#pragma unroll 8
    for (int c = 0; c < H1; c++) {
        acc += sHx[own0 + ty][c] * sWs2[c][f] + sP1[ty][c] * sWn2[c][f];
    }
    h2s[ty][f] = acc;
    __syncthreads();
    float accA = bm1[f], accB = 0.f;
#pragma unroll
    for (int c = 0; c < H2; c++) {
        float v = h2s[ty][c];
        accA += v * sWm1[c][f];
        accB += v * sWm1[H2 + c][f];
    }
    int node = nbase + ty;
    g_A[node * H2 + f] = accA;
    g_B[node * H2 + f] = accB;
    if (blk == 0 && ty == 0) {
        g_wd[f] = Wm2[f * 2 + 0] - Wm2[f * 2 + 1];
        if (f == 0) g_bd = bm2[0] - bm2[1];
    }
}

// ================ K4: edge kernel (128x128 tiles, 8x8/thread, f32x2) ================
#define TT 128
#define TSTR 132
__device__ __forceinline__ unsigned long long pk2(float x, float y) {
    unsigned long long r;
    asm("mov.b64 %0, {%1, %2};" : "=l"(r) : "r"(__float_as_uint(x)), "r"(__float_as_uint(y)));
    return r;
}
__device__ __forceinline__ void edge_step(unsigned long long& acc, unsigned long long aa,
                                          unsigned long long bb, unsigned long long ww) {
    asm("{\n\t"
        ".reg .b64 d, r;\n\t"
        ".reg .f32 lo, hi;\n\t"
        "add.rn.f32x2 d, %1, %2;\n\t"
        "mov.b64 {lo, hi}, d;\n\t"
        "max.f32 lo, lo, 0f00000000;\n\t"
        "max.f32 hi, hi, 0f00000000;\n\t"
        "mov.b64 r, {lo, hi};\n\t"
        "fma.rn.f32x2 %0, r, %3, %0;\n\t"
        "}\n"
        : "+l"(acc)
        : "l"(aa), "l"(bb), "l"(ww));
}

__global__ void __launch_bounds__(256) k_edge(float* __restrict__ out) {
    int bj = blockIdx.x, bi = blockIdx.y;
    if (bi > bj) return;
    int i0 = bi * TT, j0 = bj * TT;

    __shared__ float sAt[H2][TSTR];  // k-major
    __shared__ float sBt[H2][TSTR];
    __shared__ float swd[H2];
    __shared__ float sbd;

    int t = threadIdx.x;  // 256
    {
        const float4* gA4 = (const float4*)(g_A + (size_t)i0 * H2);
        const float4* gB4 = (const float4*)(g_B + (size_t)j0 * H2);
        for (int v = t; v < TT * 8; v += 256) {
            int r = v >> 3, c = (v & 7) * 4;
            float4 qa = gA4[v];
            sAt[c + 0][r] = qa.x; sAt[c + 1][r] = qa.y;
            sAt[c + 2][r] = qa.z; sAt[c + 3][r] = qa.w;
            float4 qb = gB4[v];
            sBt[c + 0][r] = qb.x; sBt[c + 1][r] = qb.y;
            sBt[c + 2][r] = qb.z; sBt[c + 3][r] = qb.w;
        }
        if (t < H2) swd[t] = g_wd[t];
        if (t == 0) sbd = g_bd;
    }
    __syncthreads();

    int tx = t & 15, ty = t >> 4;  // 16 x 16
    unsigned long long acc[4][8];  // (a-pair) x b
#pragma unroll
    for (int a2 = 0; a2 < 4; a2++)
#pragma unroll
        for (int b = 0; b < 8; b++) acc[a2][b] = 0ull;

#pragma unroll 4
    for (int k = 0; k < H2; k++) {
        float w = swd[k];
        unsigned long long ww = pk2(w, w);
        float4 a0 = *(const float4*)&sAt[k][ty * 8];      // 16B-aligned (stride 132)
        float4 a1 = *(const float4*)&sAt[k][ty * 8 + 4];
        unsigned long long aa[4];
        aa[0] = pk2(a0.x, a0.y);
        aa[1] = pk2(a0.z, a0.w);
        aa[2] = pk2(a1.x, a1.y);
        aa[3] = pk2(a1.z, a1.w);
#pragma unroll
        for (int b = 0; b < 8; b++) {
            float bv = sBt[k][tx + 16 * b];
            unsigned long long bb = pk2(bv, bv);
#pragma unroll
            for (int a2 = 0; a2 < 4; a2++) edge_step(acc[a2][b], aa[a2], bb, ww);
        }
    }

    float bd = sbd;
#pragma unroll
    for (int a2 = 0; a2 < 4; a2++) {
#pragma unroll
        for (int h = 0; h < 2; h++) {
            int a = a2 * 2 + h;
            int i = i0 + ty * 8 + a;
            int basei = i * (2 * NND - 1 - i) / 2;  // #edges with src < i
#pragma unroll
            for (int b = 0; b < 8; b++) {
                int j = j0 + tx + 16 * b;
                if (j > i) {
                    unsigned int bits = (h == 0) ? (unsigned int)acc[a2][b]
                                                 : (unsigned int)(acc[a2][b] >> 32);
                    float d = __uint_as_float(bits) + bd;  // z0 - z1
                    float ex = __expf(-d);
                    float p0 = __fdividef(1.f, 1.f + ex);
                    float p1 = 1.f - p0;
                    int e = basei + (j - i - 1);
                    ((float2*)out)[e] = make_float2(p0, p1);
                }
            }
        }
    }
}

// ---------------- launch ----------------
extern "C" void kernel_launch(void* const* d_in, const int* in_sizes, int n_in,
                              void* d_out, int out_size) {
    const float* x    = (const float*)d_in[0];
    const float* cent = (const float*)d_in[1];
    const float* Ws1  = (const float*)d_in[2];
    const float* Wn1  = (const float*)d_in[3];
    const float* b1   = (const float*)d_in[4];
    const float* Ws2  = (const float*)d_in[5];
    const float* Wn2  = (const float*)d_in[6];
    const float* b2   = (const float*)d_in[7];
    const float* Wm1  = (const float*)d_in[8];
    const float* bm1  = (const float*)d_in[9];
    const float* Wm2  = (const float*)d_in[10];
    const float* bm2  = (const float*)d_in[11];
    float* out = (float*)d_out;

    k_pre<<<128 + 136, 512>>>(x, cent);
    k_h1f<<<128, 512>>>(x, cent, Ws1, Wn1, b1);
    k_h2AB<<<256, 256>>>(b2, Ws2, Wn2, Wm1, bm1, Wm2, bm2);
    k_edge<<<dim3(16, 16), 256>>>(out);
}